// round 14
// baseline (speedup 1.0000x reference)
#include <cuda_runtime.h>
#include <cuda_fp16.h>
#include <math.h>
#include <stdint.h>

#define BATCH 16
#define NCLASS 10

// ---------------- scratch (static __device__, allocation-free) ----------------
__device__ float g_Whz[(size_t)BATCH * 1024 * 256];
__device__ float g_Whs[(size_t)BATCH * 1024 * 64];
__device__ float g_Zb [(size_t)BATCH * 1024 * 256];
__device__ float g_Sb [(size_t)BATCH * 1024 * 64];
__device__ float g_Tb [(size_t)BATCH * 64 * 1024];
__device__ float g_Gb [(size_t)BATCH * 64 * 64];
__device__ float g_Xp [(size_t)BATCH * 64 * 256];
__device__ float g_Ap [(size_t)BATCH * 64 * 64];
__device__ float g_f1z[BATCH * 1024];
__device__ float g_f2z[BATCH * 1024];
__device__ float g_f1s[BATCH * 1024];
__device__ float g_f2s[BATCH * 1024];
__device__ float g_mz [BATCH * 1024];
__device__ float g_iz [BATCH * 1024];
__device__ float g_ms [BATCH * 1024];
__device__ float g_is [BATCH * 1024];
__device__ double g_link, g_ent, g_tot, g_tot1, g_tot2;

// pack two floats' fp16 hi/lo splits into half2 words
__device__ __forceinline__ void pack_split(float x0, float x1, uint32_t& hw, uint32_t& lw) {
    __half h0 = __float2half_rn(x0);
    __half h1 = __float2half_rn(x1);
    float r0 = x0 - __half2float(h0);
    float r1 = x1 - __half2float(h1);
    __half l0 = __float2half_rn(r0);
    __half l1 = __float2half_rn(r1);
    hw = (uint32_t)__half_as_ushort(h0) | ((uint32_t)__half_as_ushort(h1) << 16);
    lw = (uint32_t)__half_as_ushort(l0) | ((uint32_t)__half_as_ushort(l1) << 16);
}

#define AM_NN    0
#define AM_TN    1
#define AM_FUSED 2

// ---------------- 3xFP16 split warp-MMA GEMM (near-fp32 accurate) ----------------
// C[b] = op(A[b]) * B[b] via mma.sync.m16n8k16.f16 with hi/lo split:
//   C += Ahi*Bhi + Ahi*Blo + Alo*Bhi     (lo*lo dropped, ~2^-22 relative)
// EXB: B operand exactly fp16-representable (adjacency 0/1) -> skip Ahi*Blo.
// WR x WC: warp grid (WR*WC == 8 warps of 256 threads).
template<int BM, int BN, int WR, int WC, int AM, bool RELU, bool EXB>
__global__ __launch_bounds__(256)
void mma_k(const float* __restrict__ Ag, const float* __restrict__ Bg,
           float* __restrict__ Cg, int M, int N, int K,
           long sA, long sB, long sC,
           const float* __restrict__ f1, const float* __restrict__ f2,
           const float* __restrict__ rm, const float* __restrict__ ri)
{
    static_assert(WR * WC == 8, "8 warps");
    constexpr int BK  = 16;
    constexpr int KP  = 8;
    constexpr int PAD = 8;
    constexpr int WM  = BM / WR;
    constexpr int WN  = BN / WC;
    constexpr int MT  = WM / 16;
    constexpr int NT  = WN / 8;
    constexpr int APL = (BM * KP) / 256;
    constexpr int BPL = (BN * KP) / 256;

    __shared__ uint32_t AsH[KP][BM + PAD];
    __shared__ uint32_t AsL[KP][BM + PAD];
    __shared__ uint32_t BsH[KP][BN + PAD];
    __shared__ uint32_t BsL[EXB ? 1 : KP][BN + PAD];
    __shared__ float s_f1[BM], s_m[BM], s_i[BM];

    const int b = blockIdx.z;
    const float* Ab = Ag + (long)b * sA;
    const float* Bb = Bg + (long)b * sB;
    float* Cb = Cg + (long)b * sC;

    const int bm = blockIdx.y * BM, bn = blockIdx.x * BN;
    const int tid  = threadIdx.x;
    const int warp = tid >> 5, lane = tid & 31;
    const int wm = (warp / WC) * WM, wn = (warp % WC) * WN;
    const int lg = lane >> 2, lt = lane & 3;

    const float* f2b = nullptr;
    if (AM == AM_FUSED) {
        f2b = f2 + (long)b * K;
        const float* f1b = f1 + (long)b * K;
        const float* rmb = rm + (long)b * K;
        const float* rib = ri + (long)b * K;
        for (int i = tid; i < BM; i += 256) {
            int gi = bm + i;
            if (gi < M) { s_f1[i] = f1b[gi]; s_m[i] = rmb[gi]; s_i[i] = rib[gi]; }
            else        { s_f1[i] = 0.f; s_m[i] = 0.f; s_i[i] = 1.f; }
        }
    }

    float acc[MT][NT][4];
#pragma unroll
    for (int mt = 0; mt < MT; mt++)
#pragma unroll
        for (int nt = 0; nt < NT; nt++)
#pragma unroll
            for (int q = 0; q < 4; q++) acc[mt][nt][q] = 0.f;

    float2 rA[APL], rB[BPL];
    float2 rF[(AM == AM_FUSED) ? APL : 1];

    auto loadA = [&](int k0) {
#pragma unroll
        for (int t = 0; t < APL; t++) {
            int idx = tid + 256 * t;
            if (AM == AM_TN) {
                int m = idx % BM, kp = idx / BM;
                int gm = bm + m, gk = k0 + 2 * kp;
                float x0 = (gm < M && gk     < K) ? Ab[(long)gk * M + gm]       : 0.f;
                float x1 = (gm < M && gk + 1 < K) ? Ab[(long)(gk + 1) * M + gm] : 0.f;
                rA[t] = make_float2(x0, x1);
            } else {
                int kp = idx & 7, m = idx >> 3;
                int gm = bm + m, gk = k0 + 2 * kp;
                float x0 = 0.f, x1 = 0.f;
                if (gm < M) {
                    if (gk + 1 < K) {
                        float2 v = *reinterpret_cast<const float2*>(&Ab[(long)gm * K + gk]);
                        x0 = v.x; x1 = v.y;
                    } else if (gk < K) {
                        x0 = Ab[(long)gm * K + gk];
                    }
                }
                rA[t] = make_float2(x0, x1);
                if (AM == AM_FUSED) {
                    float fa = 0.f, fb = 0.f;
                    if (gk + 1 < K) {
                        float2 v = *reinterpret_cast<const float2*>(&f2b[gk]);
                        fa = v.x; fb = v.y;
                    } else if (gk < K) {
                        fa = f2b[gk];
                    }
                    rF[t] = make_float2(fa, fb);
                }
            }
        }
    };
    auto loadB = [&](int k0) {
#pragma unroll
        for (int t = 0; t < BPL; t++) {
            int idx = tid + 256 * t;
            int n = idx % BN, kp = idx / BN;
            int gn = bn + n, gk = k0 + 2 * kp;
            float x0 = (gn < N && gk     < K) ? Bb[(long)gk * N + gn]       : 0.f;
            float x1 = (gn < N && gk + 1 < K) ? Bb[(long)(gk + 1) * N + gn] : 0.f;
            rB[t] = make_float2(x0, x1);
        }
    };
    auto storeAB = [&](int k0) {
#pragma unroll
        for (int t = 0; t < APL; t++) {
            int idx = tid + 256 * t;
            int kp, m;
            if (AM == AM_TN) { m = idx % BM; kp = idx / BM; }
            else             { kp = idx & 7; m = idx >> 3; }
            float x0 = rA[t].x, x1 = rA[t].y;
            if (AM == AM_FUSED) {
                int gk = k0 + 2 * kp;
                float e0 = s_f1[m] + rF[t].x; e0 = (e0 > 0.f) ? e0 : 0.2f * e0;
                if (!(x0 > 0.f)) e0 = -9e15f;
                float e1 = s_f1[m] + rF[t].y; e1 = (e1 > 0.f) ? e1 : 0.2f * e1;
                if (!(x1 > 0.f)) e1 = -9e15f;
                x0 = (gk     < K) ? __expf(e0 - s_m[m]) * s_i[m] : 0.f;
                x1 = (gk + 1 < K) ? __expf(e1 - s_m[m]) * s_i[m] : 0.f;
            }
            uint32_t hw, lw; pack_split(x0, x1, hw, lw);
            AsH[kp][m] = hw; AsL[kp][m] = lw;
        }
#pragma unroll
        for (int t = 0; t < BPL; t++) {
            int idx = tid + 256 * t;
            int n = idx % BN, kp = idx / BN;
            uint32_t hw, lw; pack_split(rB[t].x, rB[t].y, hw, lw);
            BsH[kp][n] = hw;
            if (!EXB) BsL[kp][n] = lw;
        }
    };

    loadA(0); loadB(0);
    __syncthreads();

    for (int k0 = 0; k0 < K; k0 += BK) {
        storeAB(k0);
        __syncthreads();
        if (k0 + BK < K) { loadA(k0 + BK); loadB(k0 + BK); }

        uint32_t ah[MT][4], al[MT][4], bh[NT][2], bl[NT][2];
#pragma unroll
        for (int mt = 0; mt < MT; mt++) {
            int r = wm + mt * 16;
            ah[mt][0] = AsH[lt    ][r + lg];
            ah[mt][1] = AsH[lt    ][r + lg + 8];
            ah[mt][2] = AsH[lt + 4][r + lg];
            ah[mt][3] = AsH[lt + 4][r + lg + 8];
            al[mt][0] = AsL[lt    ][r + lg];
            al[mt][1] = AsL[lt    ][r + lg + 8];
            al[mt][2] = AsL[lt + 4][r + lg];
            al[mt][3] = AsL[lt + 4][r + lg + 8];
        }
#pragma unroll
        for (int nt = 0; nt < NT; nt++) {
            int cidx = wn + nt * 8 + lg;
            bh[nt][0] = BsH[lt    ][cidx];
            bh[nt][1] = BsH[lt + 4][cidx];
            if (!EXB) {
                bl[nt][0] = BsL[lt    ][cidx];
                bl[nt][1] = BsL[lt + 4][cidx];
            }
        }
#define MMA_STEP(AF, BF)                                                        \
        asm volatile(                                                           \
            "mma.sync.aligned.m16n8k16.row.col.f32.f16.f16.f32 "                \
            "{%0,%1,%2,%3}, {%4,%5,%6,%7}, {%8,%9}, {%0,%1,%2,%3};"             \
            : "+f"(acc[mt][nt][0]), "+f"(acc[mt][nt][1]),                       \
              "+f"(acc[mt][nt][2]), "+f"(acc[mt][nt][3])                        \
            : "r"(AF[mt][0]), "r"(AF[mt][1]), "r"(AF[mt][2]), "r"(AF[mt][3]),   \
              "r"(BF[nt][0]), "r"(BF[nt][1]))
#pragma unroll
        for (int mt = 0; mt < MT; mt++)
#pragma unroll
            for (int nt = 0; nt < NT; nt++) {
                if (!EXB) MMA_STEP(ah, bl);
                MMA_STEP(al, bh);
                MMA_STEP(ah, bh);
            }
#undef MMA_STEP
        __syncthreads();
    }

#pragma unroll
    for (int mt = 0; mt < MT; mt++) {
#pragma unroll
        for (int nt = 0; nt < NT; nt++) {
            int gm = bm + wm + mt * 16 + lg;
            int gn = bn + wn + nt * 8 + 2 * lt;
            float v0 = acc[mt][nt][0], v1 = acc[mt][nt][1];
            float v2 = acc[mt][nt][2], v3 = acc[mt][nt][3];
            if (RELU) {
                v0 = v0 > 0.f ? v0 : 0.f;  v1 = v1 > 0.f ? v1 : 0.f;
                v2 = v2 > 0.f ? v2 : 0.f;  v3 = v3 > 0.f ? v3 : 0.f;
            }
            if (gm < M) {
                if (gn     < N) Cb[(long)gm * N + gn    ] = v0;
                if (gn + 1 < N) Cb[(long)gm * N + gn + 1] = v1;
            }
            if (gm + 8 < M) {
                if (gn     < N) Cb[(long)(gm + 8) * N + gn    ] = v2;
                if (gn + 1 < N) Cb[(long)(gm + 8) * N + gn + 1] = v3;
            }
        }
    }
}

// ---------------- row stats (layer 0 only) ----------------
__global__ void rowstat_k(const float* __restrict__ A,
                          const float* __restrict__ f1z, const float* __restrict__ f2z,
                          const float* __restrict__ f1s, const float* __restrict__ f2s,
                          float* __restrict__ mz, float* __restrict__ iz,
                          float* __restrict__ ms, float* __restrict__ is_, int N)
{
    int row = blockIdx.x;
    int b = row / N;
    const float* Ar = A + (size_t)row * N;
    const float* f2zb = f2z + (size_t)b * N;
    const float* f2sb = f2s + (size_t)b * N;
    float fz = f1z[row], fs = f1s[row];
    int t = threadIdx.x;
    float ez[4], es[4];
    float mzl = -1e30f, msl = -1e30f;
    double ss = 0.0;
#pragma unroll
    for (int it = 0; it < 4; it++) {
        int j = t + it * 256;
        float vz = -9e15f, vs = -9e15f;
        if (j < N) {
            float a = Ar[j];
            ss += (double)a * (double)a;
            bool on = a > 0.f;
            float xz = fz + f2zb[j];
            float xs = fs + f2sb[j];
            float lz = (xz > 0.f) ? xz : 0.2f * xz;
            float ls = (xs > 0.f) ? xs : 0.2f * xs;
            vz = on ? lz : -9e15f;
            vs = on ? ls : -9e15f;
        }
        ez[it] = vz; es[it] = vs;
        mzl = fmaxf(mzl, vz); msl = fmaxf(msl, vs);
    }
    __shared__ float sh[256];
    sh[t] = mzl; __syncthreads();
    for (int s = 128; s > 0; s >>= 1) { if (t < s) sh[t] = fmaxf(sh[t], sh[t + s]); __syncthreads(); }
    float Mz = sh[0]; __syncthreads();
    sh[t] = msl; __syncthreads();
    for (int s = 128; s > 0; s >>= 1) { if (t < s) sh[t] = fmaxf(sh[t], sh[t + s]); __syncthreads(); }
    float Ms = sh[0]; __syncthreads();

    float sz = 0.f, ssum = 0.f;
#pragma unroll
    for (int it = 0; it < 4; it++) {
        int j = t + it * 256;
        if (j < N) { sz += __expf(ez[it] - Mz); ssum += __expf(es[it] - Ms); }
    }
    sh[t] = sz; __syncthreads();
    for (int s = 128; s > 0; s >>= 1) { if (t < s) sh[t] += sh[t + s]; __syncthreads(); }
    float Sz = sh[0]; __syncthreads();
    sh[t] = ssum; __syncthreads();
    for (int s = 128; s > 0; s >>= 1) { if (t < s) sh[t] += sh[t + s]; __syncthreads(); }
    float Ss = sh[0]; __syncthreads();

    __shared__ double dh[256];
    dh[t] = ss; __syncthreads();
    for (int s = 128; s > 0; s >>= 1) { if (t < s) dh[t] += dh[t + s]; __syncthreads(); }

    if (t == 0) {
        mz[row] = Mz; iz[row] = 1.f / Sz;
        ms[row] = Ms; is_[row] = 1.f / Ss;
        atomicAdd(&g_tot, dh[0]);
    }
}

// ---------------- f1/f2, dual-target (blockIdx.y routes) ----------------
__device__ __forceinline__ void fvec_body(const float* __restrict__ Wh,
                                          const float* __restrict__ a,
                                          float* __restrict__ f1, float* __restrict__ f2,
                                          int rows, int F)
{
    int w = (blockIdx.x * blockDim.x + threadIdx.x) >> 5;
    int lane = threadIdx.x & 31;
    if (w >= rows) return;
    const float* p = Wh + (size_t)w * F;
    float s1 = 0.f, s2 = 0.f;
    for (int f = lane; f < F; f += 32) {
        float v = p[f];
        s1 += v * a[f];
        s2 += v * a[F + f];
    }
#pragma unroll
    for (int o = 16; o > 0; o >>= 1) {
        s1 += __shfl_down_sync(0xffffffffu, s1, o);
        s2 += __shfl_down_sync(0xffffffffu, s2, o);
    }
    if (lane == 0) { f1[w] = s1; f2[w] = s2; }
}

__global__ void fvec2_k(const float* WhA, const float* aA, float* f1A, float* f2A, int FA,
                        const float* WhB, const float* aB, float* f1B, float* f2B, int FB,
                        int rows)
{
    if (blockIdx.y == 0) fvec_body(WhA, aA, f1A, f2A, rows, FA);
    else                 fvec_body(WhB, aB, f1B, f2B, rows, FB);
}

// ---------------- softmax over c + entropy (layer 0) ----------------
__global__ void softmax_c_ent(float* __restrict__ S, int rows, int c, double inv_rows)
{
    int w = (blockIdx.x * blockDim.x + threadIdx.x) >> 5;
    int lane = threadIdx.x & 31;
    if (w >= rows) return;
    float* p = S + (size_t)w * c;
    float v[2] = {-1e30f, -1e30f};
    float m = -1e30f;
#pragma unroll
    for (int i = 0; i < 2; i++) {
        int f = lane + 32 * i;
        if (f < c) { v[i] = p[f]; m = fmaxf(m, v[i]); }
    }
#pragma unroll
    for (int o = 16; o > 0; o >>= 1) m = fmaxf(m, __shfl_xor_sync(0xffffffffu, m, o));
    float s = 0.f;
#pragma unroll
    for (int i = 0; i < 2; i++) {
        int f = lane + 32 * i;
        if (f < c) { v[i] = __expf(v[i] - m); s += v[i]; }
    }
#pragma unroll
    for (int o = 16; o > 0; o >>= 1) s += __shfl_xor_sync(0xffffffffu, s, o);
    float inv = 1.f / s;
    double erow = 0.0;
#pragma unroll
    for (int i = 0; i < 2; i++) {
        int f = lane + 32 * i;
        if (f < c) {
            float q = v[i] * inv;
            p[f] = q;
            erow += -(double)q * (double)logf(q + 1e-15f);
        }
    }
#pragma unroll
    for (int o = 16; o > 0; o >>= 1) erow += __shfl_down_sync(0xffffffffu, erow, o);
    if (lane == 0) atomicAdd(&g_ent, erow * inv_rows);
}

__global__ void k_zero_losses() { g_link = 0.0; g_ent = 0.0; g_tot = 0.0; g_tot1 = 0.0; g_tot2 = 0.0; }

// ---------------- fused layers 1+2 tail (fp32, one block per batch) ----------------
#define FUSED_SMEM_FLOATS 49664

__global__ __launch_bounds__(256)
void fused_tail_k(const float* __restrict__ Whz1g, const float* __restrict__ Whs1g,
                  const float* __restrict__ A1g,
                  const float* __restrict__ f1zg, const float* __restrict__ f2zg,
                  const float* __restrict__ f1sg, const float* __restrict__ f2sg,
                  const float* __restrict__ Wg2, const float* __restrict__ ag2,
                  const float* __restrict__ Ws2, const float* __restrict__ as2,
                  const float* __restrict__ Wd, const float* __restrict__ bd,
                  float* __restrict__ out, int out_size)
{
    const int b = blockIdx.x, tid = threadIdx.x;
    const int warp = tid >> 5, lane = tid & 31;
    extern __shared__ float sm[];
    float* sWh  = sm;
    float* sZ   = sWh  + 16384;
    float* sA   = sZ   + 16384;
    float* sE   = sA   + 4096;
    float* sX2  = sE   + 4096;
    float* sWh2 = sX2  + 2048;
    float* sZ2  = sWh2 + 2048;
    float* sWhs = sZ2  + 2048;
    float* sS   = sWhs + 512;
    float* sT   = sS   + 512;
    float* sf1  = sT   + 512;
    float* sf2  = sf1  + 64;
    float* sg1  = sf2  + 64;
    float* sg2  = sg1  + 64;
    float* sA2  = sg2  + 64;
    float* sX3  = sA2  + 64;
    float* sWhs2= sX3  + 256;
    float* sP2  = sWhs2+ 8;
    float* sf1b = sP2  + 64;
    float* sf2b = sf1b + 8;
    float* sf1c = sf2b + 8;
    float* sf2c = sf1c + 8;
    float* sred = sf2c + 8;

    for (int i = tid; i < 64 * 256; i += 256) sWh[i] = Whz1g[(size_t)b * 16384 + i];
    for (int i = tid; i < 4096; i += 256)     sA[i]  = A1g [(size_t)b * 4096 + i];
    for (int i = tid; i < 512; i += 256)      sWhs[i] = Whs1g[(size_t)b * 512 + i];
    if (tid < 64) {
        sf1[tid] = f1zg[b * 64 + tid]; sf2[tid] = f2zg[b * 64 + tid];
        sg1[tid] = f1sg[b * 64 + tid]; sg2[tid] = f2sg[b * 64 + tid];
    }
    __syncthreads();

    for (int r = warp * 8; r < warp * 8 + 8; r++) {
        float f1i = sf1[r];
        float e0, e1;
        {
            int j = lane;
            float x = f1i + sf2[j]; x = (x > 0.f) ? x : 0.2f * x;
            e0 = (sA[r * 64 + j] > 0.f) ? x : -9e15f;
            j = lane + 32;
            x = f1i + sf2[j]; x = (x > 0.f) ? x : 0.2f * x;
            e1 = (sA[r * 64 + j] > 0.f) ? x : -9e15f;
        }
        float m = fmaxf(e0, e1);
#pragma unroll
        for (int o = 16; o > 0; o >>= 1) m = fmaxf(m, __shfl_xor_sync(0xffffffffu, m, o));
        float p0 = __expf(e0 - m), p1 = __expf(e1 - m);
        float s = p0 + p1;
#pragma unroll
        for (int o = 16; o > 0; o >>= 1) s += __shfl_xor_sync(0xffffffffu, s, o);
        float inv = 1.f / s;
        sE[r * 64 + lane] = p0 * inv;
        sE[r * 64 + lane + 32] = p1 * inv;
    }
    __syncthreads();

    for (int n0 = 0; n0 < 64; n0 += 16) {
        float acc[16];
#pragma unroll
        for (int i = 0; i < 16; i++) acc[i] = 0.f;
        for (int k = 0; k < 64; k++) {
            float whv = sWh[k * 256 + tid];
#pragma unroll
            for (int i = 0; i < 16; i++) acc[i] += sE[(n0 + i) * 64 + k] * whv;
        }
#pragma unroll
        for (int i = 0; i < 16; i++) sZ[(n0 + i) * 256 + tid] = fmaxf(acc[i], 0.f);
    }
    __syncthreads();

    for (int r = warp * 8; r < warp * 8 + 8; r++) {
        float f1i = sg1[r];
        float e0, e1;
        {
            int j = lane;
            float x = f1i + sg2[j]; x = (x > 0.f) ? x : 0.2f * x;
            e0 = (sA[r * 64 + j] > 0.f) ? x : -9e15f;
            j = lane + 32;
            x = f1i + sg2[j]; x = (x > 0.f) ? x : 0.2f * x;
            e1 = (sA[r * 64 + j] > 0.f) ? x : -9e15f;
        }
        float m = fmaxf(e0, e1);
#pragma unroll
        for (int o = 16; o > 0; o >>= 1) m = fmaxf(m, __shfl_xor_sync(0xffffffffu, m, o));
        float p0 = __expf(e0 - m), p1 = __expf(e1 - m);
        float s = p0 + p1;
#pragma unroll
        for (int o = 16; o > 0; o >>= 1) s += __shfl_xor_sync(0xffffffffu, s, o);
        float inv = 1.f / s;
        sE[r * 64 + lane] = p0 * inv;
        sE[r * 64 + lane + 32] = p1 * inv;
    }
    __syncthreads();

    for (int idx = tid; idx < 512; idx += 256) {
        int n = idx >> 3, cc = idx & 7;
        float s = 0.f;
        for (int j = 0; j < 64; j++) s += sE[n * 64 + j] * sWhs[j * 8 + cc];
        sS[idx] = fmaxf(s, 0.f);
    }
    __syncthreads();

    if (tid < 64) {
        float v[8]; float m = -1e30f;
#pragma unroll
        for (int c = 0; c < 8; c++) { v[c] = sS[tid * 8 + c]; m = fmaxf(m, v[c]); }
        float s = 0.f;
#pragma unroll
        for (int c = 0; c < 8; c++) { v[c] = __expf(v[c] - m); s += v[c]; }
        float inv = 1.f / s;
        float ent = 0.f;
#pragma unroll
        for (int c = 0; c < 8; c++) {
            float q = v[c] * inv;
            sS[tid * 8 + c] = q;
            ent += -q * logf(q + 1e-15f);
        }
        sred[tid] = ent;
    }
    __syncthreads();
    if (tid == 0) {
        double e = 0.0;
        for (int i = 0; i < 64; i++) e += (double)sred[i];
        atomicAdd(&g_ent, e / 1024.0);
    }

    for (int idx = tid; idx < 2048; idx += 256) {
        int c = idx >> 8, f = idx & 255;
        float s = 0.f;
        for (int n = 0; n < 64; n++) s += sS[n * 8 + c] * sZ[n * 256 + f];
        sX2[idx] = s;
    }
    for (int idx = tid; idx < 512; idx += 256) {
        int c = idx >> 6, j = idx & 63;
        float s = 0.f;
        for (int n = 0; n < 64; n++) s += sS[n * 8 + c] * sA[n * 64 + j];
        sT[idx] = s;
    }
    __syncthreads();
    if (tid < 64) {
        int c = tid >> 3, d = tid & 7;
        float s = 0.f;
        for (int j = 0; j < 64; j++) s += sT[c * 64 + j] * sS[j * 8 + d];
        sA2[tid] = s;
    }
    {
        float lsum = 0.f;
        for (int idx = tid; idx < 4096; idx += 256) {
            int i = idx >> 6, j = idx & 63;
            float d = 0.f;
#pragma unroll
            for (int c = 0; c < 8; c++) d += sS[i * 8 + c] * sS[j * 8 + c];
            float df = sA[idx] - d;
            lsum += df * df;
        }
        sred[tid] = lsum; __syncthreads();
        for (int r = 128; r > 0; r >>= 1) { if (tid < r) sred[tid] += sred[tid + r]; __syncthreads(); }
        if (tid == 0) atomicAdd(&g_tot1, (double)sred[0]);
    }
    __syncthreads();

    {
        float acc[8];
#pragma unroll
        for (int i = 0; i < 8; i++) acc[i] = 0.f;
        for (int k = 0; k < 256; k++) {
            float wg = Wg2[k * 256 + tid];
#pragma unroll
            for (int n = 0; n < 8; n++) acc[n] += sX2[n * 256 + k] * wg;
        }
#pragma unroll
        for (int n = 0; n < 8; n++) sWh2[n * 256 + tid] = acc[n];
    }
    {
        float p = 0.f;
        for (int k = lane; k < 256; k += 32) p += sX2[warp * 256 + k] * Ws2[k];
#pragma unroll
        for (int o = 16; o > 0; o >>= 1) p += __shfl_down_sync(0xffffffffu, p, o);
        if (lane == 0) sWhs2[warp] = p;
    }
    __syncthreads();
    {
        float p1 = 0.f, p2 = 0.f;
        for (int k = lane; k < 256; k += 32) {
            float v = sWh2[warp * 256 + k];
            p1 += v * ag2[k];
            p2 += v * ag2[256 + k];
        }
#pragma unroll
        for (int o = 16; o > 0; o >>= 1) {
            p1 += __shfl_down_sync(0xffffffffu, p1, o);
            p2 += __shfl_down_sync(0xffffffffu, p2, o);
        }
        if (lane == 0) { sf1b[warp] = p1; sf2b[warp] = p2; }
    }
    if (tid < 8) {
        sf1c[tid] = sWhs2[tid] * as2[0];
        sf2c[tid] = sWhs2[tid] * as2[1];
    }
    __syncthreads();
    if (tid < 8) {
        float e[8]; float m = -1e30f;
#pragma unroll
        for (int j = 0; j < 8; j++) {
            float x = sf1b[tid] + sf2b[j]; x = (x > 0.f) ? x : 0.2f * x;
            e[j] = (sA2[tid * 8 + j] > 0.f) ? x : -9e15f;
            m = fmaxf(m, e[j]);
        }
        float s = 0.f;
#pragma unroll
        for (int j = 0; j < 8; j++) { e[j] = __expf(e[j] - m); s += e[j]; }
        float inv = 1.f / s;
#pragma unroll
        for (int j = 0; j < 8; j++) sP2[tid * 8 + j] = e[j] * inv;
    }
    __syncthreads();
    {
#pragma unroll
        for (int n = 0; n < 8; n++) {
            float z = 0.f;
#pragma unroll
            for (int k = 0; k < 8; k++) z += sP2[n * 8 + k] * sWh2[k * 256 + tid];
            sZ2[n * 256 + tid] = fmaxf(z, 0.f);
        }
    }
    __syncthreads();
    {
        float s = 0.f;
#pragma unroll
        for (int n = 0; n < 8; n++) s += sZ2[n * 256 + tid];
        sX3[tid] = s;
    }
    if (tid < 64) {
        float d = sA2[tid] - 1.f;
        sred[tid] = d * d;
    } else sred[tid] = 0.f;
    __syncthreads();
    for (int r = 128; r > 0; r >>= 1) { if (tid < r) sred[tid] += sred[tid + r]; __syncthreads(); }
    if (tid == 0) {
        atomicAdd(&g_tot2, (double)sred[0]);
        float a3 = 0.f;
        for (int i = 0; i < 64; i++) a3 += sA2[i];
        if (160 + b < out_size) out[160 + b] = a3;
    }
    __syncthreads();
    if (tid < NCLASS) {
        float v = bd[tid];
        for (int f = 0; f < 256; f++) v += sX3[f] * Wd[f * NCLASS + tid];
        if (b * NCLASS + tid < out_size) out[b * NCLASS + tid] = v;
    }
}

// ---------------- final: link0 reduction + write losses (merged) ----------------
__global__ void tail_fin(const float* __restrict__ Ap, const float* __restrict__ G,
                         float* __restrict__ out, int out_size)
{
    int t = threadIdx.x;
    double s = 0.0;
    for (int idx = t; idx < BATCH * 64; idx += 256) {
        int b = idx / 64, j = idx % 64;
        s += -2.0 * (double)Ap[((long)b * 64 + j) * 64 + j];
    }
    for (int idx = t; idx < BATCH * 64 * 64; idx += 256) {
        double g = G[idx]; s += g * g;
    }
    __shared__ double sh[256];
    sh[t] = s; __syncthreads();
    for (int r = 128; r > 0; r >>= 1) { if (t < r) sh[t] += sh[t + r]; __syncthreads(); }
    if (t == 0) {
        double v0 = g_tot + sh[0];
        double t1 = g_tot1, t2 = g_tot2;
        double link = sqrt(v0 > 0.0 ? v0 : 0.0) / (double)((long)BATCH * 1024 * 1024)
                    + sqrt(t1 > 0.0 ? t1 : 0.0) / 65536.0
                    + sqrt(t2 > 0.0 ? t2 : 0.0) / 1024.0;
        if (176 < out_size) out[176] = (float)link;
        if (177 < out_size) out[177] = (float)g_ent;
    }
}

#define NOF nullptr, nullptr, nullptr, nullptr

extern "C" void kernel_launch(void* const* d_in, const int* in_sizes, int n_in,
                              void* d_out, int out_size)
{
    (void)in_sizes; (void)n_in;
    const float* X  = (const float*)d_in[0];
    const float* A  = (const float*)d_in[1];
    const float* Wg0 = (const float*)d_in[2];
    const float* ag0 = (const float*)d_in[3];
    const float* Ws0 = (const float*)d_in[4];
    const float* as0 = (const float*)d_in[5];
    const float* Wg1 = (const float*)d_in[6];
    const float* ag1 = (const float*)d_in[7];
    const float* Ws1 = (const float*)d_in[8];
    const float* as1 = (const float*)d_in[9];
    const float* Wg2 = (const float*)d_in[10];
    const float* ag2 = (const float*)d_in[11];
    const float* Ws2 = (const float*)d_in[12];
    const float* as2 = (const float*)d_in[13];
    const float* Wd = (const float*)d_in[14];
    const float* bd = (const float*)d_in[15];
    float* out = (float*)d_out;

    float *whz, *whs, *z, *s, *t, *gg, *xp, *ap;
    float *f1z, *f2z, *f1s, *f2s, *mz, *iz, *ms, *is_;
    cudaGetSymbolAddress((void**)&whz, g_Whz);
    cudaGetSymbolAddress((void**)&whs, g_Whs);
    cudaGetSymbolAddress((void**)&z,   g_Zb);
    cudaGetSymbolAddress((void**)&s,   g_Sb);
    cudaGetSymbolAddress((void**)&t,   g_Tb);
    cudaGetSymbolAddress((void**)&gg,  g_Gb);
    cudaGetSymbolAddress((void**)&xp,  g_Xp);
    cudaGetSymbolAddress((void**)&ap,  g_Ap);
    cudaGetSymbolAddress((void**)&f1z, g_f1z);
    cudaGetSymbolAddress((void**)&f2z, g_f2z);
    cudaGetSymbolAddress((void**)&f1s, g_f1s);
    cudaGetSymbolAddress((void**)&f2s, g_f2s);
    cudaGetSymbolAddress((void**)&mz,  g_mz);
    cudaGetSymbolAddress((void**)&iz,  g_iz);
    cudaGetSymbolAddress((void**)&ms,  g_ms);
    cudaGetSymbolAddress((void**)&is_, g_is);

    static bool attr_set = false;
    const int FUSED_SMEM = FUSED_SMEM_FLOATS * (int)sizeof(float);
    if (!attr_set) {
        cudaFuncSetAttribute(fused_tail_k, cudaFuncAttributeMaxDynamicSharedMemorySize, FUSED_SMEM);
        attr_set = true;
    }

    k_zero_losses<<<1, 1>>>();

    // ================= layer 0: N=1024, Fin=128, Fz=256, c=64 =================
    const int N0 = 1024;
    {   // Wh_z = X @ Wg0
        dim3 g(2, 8, BATCH);
        mma_k<128, 128, 2, 4, AM_NN, false, false><<<g, 256>>>(X, Wg0, whz, N0, 256, 128,
            (long)N0 * 128, 0, (long)N0 * 256, NOF);
    }
    {   // Wh_s = X @ Ws0
        dim3 g(1, 8, BATCH);
        mma_k<128, 64, 2, 4, AM_NN, false, false><<<g, 256>>>(X, Ws0, whs, N0, 64, 128,
            (long)N0 * 128, 0, (long)N0 * 64, NOF);
    }
    {   // fvec z & s in one launch
        int rows = BATCH * N0;
        dim3 g((rows * 32 + 255) / 256, 2);
        fvec2_k<<<g, 256>>>(whz, ag0, f1z, f2z, 256, whs, as0, f1s, f2s, 64, rows);
    }
    rowstat_k<<<BATCH * N0, 256>>>(A, f1z, f2z, f1s, f2s, mz, iz, ms, is_, N0);

    {   // Z = relu(Pz @ Whz) — BN=256 covers Fz in ONE block: P generated once
        dim3 g(1, 16, BATCH);
        mma_k<64, 256, 2, 4, AM_FUSED, true, false><<<g, 256>>>(A, whz, z, N0, 256, N0,
            (long)N0 * N0, (long)N0 * 256, (long)N0 * 256, f1z, f2z, mz, iz);
    }
    {   // S_pre = relu(Ps @ Whs) — single N-block already
        dim3 g(1, 8, BATCH);
        mma_k<128, 64, 2, 4, AM_FUSED, true, false><<<g, 256>>>(A, whs, s, N0, 64, N0,
            (long)N0 * N0, (long)N0 * 64, (long)N0 * 64, f1s, f2s, ms, is_);
    }
    softmax_c_ent<<<(BATCH * N0 + 7) / 8, 256>>>(s, BATCH * N0, 64, 1.0 / (double)(BATCH * N0));
    {   // T = S^T A (EXB: A exactly fp16)
        dim3 g(8, 1, BATCH);
        mma_k<64, 128, 2, 4, AM_TN, false, true><<<g, 256>>>(s, A, t, 64, N0, N0,
            (long)N0 * 64, (long)N0 * N0, (long)64 * N0, NOF);
    }
    {   // A1 = T @ S
        dim3 g(1, 1, BATCH);
        mma_k<64, 128, 2, 4, AM_NN, false, false><<<g, 256>>>(t, s, ap, 64, 64, N0,
            (long)64 * N0, (long)N0 * 64, (long)64 * 64, NOF);
    }
    {   // X1 = S^T Z
        dim3 g(2, 1, BATCH);
        mma_k<64, 128, 2, 4, AM_TN, false, false><<<g, 256>>>(s, z, xp, 64, 256, N0,
            (long)N0 * 64, (long)N0 * 256, (long)64 * 256, NOF);
    }
    {   // G = S^T S
        dim3 g(1, 1, BATCH);
        mma_k<64, 128, 2, 4, AM_TN, false, false><<<g, 256>>>(s, s, gg, 64, 64, N0,
            (long)N0 * 64, (long)N0 * 64, (long)64 * 64, NOF);
    }

    // ================= layer 1 front (GEMMs + fvec), rest fused =================
    {   // Whz1 = X1 @ Wg1
        dim3 g(2, 1, BATCH);
        mma_k<128, 128, 2, 4, AM_NN, false, false><<<g, 256>>>(xp, Wg1, whz, 64, 256, 256,
            (long)64 * 256, 0, (long)64 * 256, NOF);
    }
    {   // Whs1 = X1 @ Ws1
        dim3 g(1, 1, BATCH);
        mma_k<128, 64, 2, 4, AM_NN, false, false><<<g, 256>>>(xp, Ws1, whs, 64, 8, 256,
            (long)64 * 256, 0, (long)64 * 8, NOF);
    }
    {   // fvec z & s in one launch
        int rows = BATCH * 64;
        dim3 g((rows * 32 + 255) / 256, 2);
        fvec2_k<<<g, 256>>>(whz, ag1, f1z, f2z, 256, whs, as1, f1s, f2s, 8, rows);
    }
    fused_tail_k<<<BATCH, 256, FUSED_SMEM>>>(whz, whs, ap, f1z, f2z, f1s, f2s,
                                             Wg2, ag2, Ws2, as2, Wd, bd, out, out_size);
    tail_fin<<<1, 256>>>(ap, gg, out, out_size);
}

// round 15
// speedup vs baseline: 1.2121x; 1.2121x over previous
#include <cuda_runtime.h>
#include <cuda_fp16.h>
#include <math.h>
#include <stdint.h>

#define BATCH 16
#define NCLASS 10

// ---------------- scratch (static __device__, allocation-free) ----------------
__device__ float g_Whz[(size_t)BATCH * 1024 * 256];
__device__ float g_Whs[(size_t)BATCH * 1024 * 64];
__device__ float g_Zb [(size_t)BATCH * 1024 * 256];
__device__ float g_Sb [(size_t)BATCH * 1024 * 64];
__device__ float g_Tb [(size_t)BATCH * 64 * 1024];
__device__ float g_Gb [(size_t)BATCH * 64 * 64];
__device__ float g_Xp [(size_t)BATCH * 64 * 256];
__device__ float g_Ap [(size_t)BATCH * 64 * 64];
__device__ float g_f1z[BATCH * 1024];
__device__ float g_f2z[BATCH * 1024];
__device__ float g_f1s[BATCH * 1024];
__device__ float g_f2s[BATCH * 1024];
__device__ float g_mz [BATCH * 1024];
__device__ float g_iz [BATCH * 1024];
__device__ float g_ms [BATCH * 1024];
__device__ float g_is [BATCH * 1024];
__device__ double g_link, g_ent, g_tot, g_tot1, g_tot2;

// pack two floats' fp16 hi/lo splits into half2 words
__device__ __forceinline__ void pack_split(float x0, float x1, uint32_t& hw, uint32_t& lw) {
    __half h0 = __float2half_rn(x0);
    __half h1 = __float2half_rn(x1);
    float r0 = x0 - __half2float(h0);
    float r1 = x1 - __half2float(h1);
    __half l0 = __float2half_rn(r0);
    __half l1 = __float2half_rn(r1);
    hw = (uint32_t)__half_as_ushort(h0) | ((uint32_t)__half_as_ushort(h1) << 16);
    lw = (uint32_t)__half_as_ushort(l0) | ((uint32_t)__half_as_ushort(l1) << 16);
}

#define AM_NN    0
#define AM_TN    1
#define AM_FUSED 2

// ---------------- 3xFP16 split warp-MMA GEMM (near-fp32 accurate) ----------------
template<int BM, int BN, int WR, int WC, int AM, bool RELU, bool EXB>
__global__ __launch_bounds__(256)
void mma_k(const float* __restrict__ Ag, const float* __restrict__ Bg,
           float* __restrict__ Cg, int M, int N, int K,
           long sA, long sB, long sC,
           const float* __restrict__ f1, const float* __restrict__ f2,
           const float* __restrict__ rm, const float* __restrict__ ri)
{
    static_assert(WR * WC == 8, "8 warps");
    constexpr int BK  = 16;
    constexpr int KP  = 8;
    constexpr int PAD = 8;
    constexpr int WM  = BM / WR;
    constexpr int WN  = BN / WC;
    constexpr int MT  = WM / 16;
    constexpr int NT  = WN / 8;
    constexpr int APL = (BM * KP) / 256;
    constexpr int BPL = (BN * KP) / 256;

    __shared__ uint32_t AsH[KP][BM + PAD];
    __shared__ uint32_t AsL[KP][BM + PAD];
    __shared__ uint32_t BsH[KP][BN + PAD];
    __shared__ uint32_t BsL[EXB ? 1 : KP][BN + PAD];
    __shared__ float s_f1[BM], s_m[BM], s_i[BM];

    const int b = blockIdx.z;
    const float* Ab = Ag + (long)b * sA;
    const float* Bb = Bg + (long)b * sB;
    float* Cb = Cg + (long)b * sC;

    const int bm = blockIdx.y * BM, bn = blockIdx.x * BN;
    const int tid  = threadIdx.x;
    const int warp = tid >> 5, lane = tid & 31;
    const int wm = (warp / WC) * WM, wn = (warp % WC) * WN;
    const int lg = lane >> 2, lt = lane & 3;

    const float* f2b = nullptr;
    if (AM == AM_FUSED) {
        f2b = f2 + (long)b * K;
        const float* f1b = f1 + (long)b * K;
        const float* rmb = rm + (long)b * K;
        const float* rib = ri + (long)b * K;
        for (int i = tid; i < BM; i += 256) {
            int gi = bm + i;
            if (gi < M) { s_f1[i] = f1b[gi]; s_m[i] = rmb[gi]; s_i[i] = rib[gi]; }
            else        { s_f1[i] = 0.f; s_m[i] = 0.f; s_i[i] = 1.f; }
        }
    }

    float acc[MT][NT][4];
#pragma unroll
    for (int mt = 0; mt < MT; mt++)
#pragma unroll
        for (int nt = 0; nt < NT; nt++)
#pragma unroll
            for (int q = 0; q < 4; q++) acc[mt][nt][q] = 0.f;

    float2 rA[APL], rB[BPL];
    float2 rF[(AM == AM_FUSED) ? APL : 1];

    auto loadA = [&](int k0) {
#pragma unroll
        for (int t = 0; t < APL; t++) {
            int idx = tid + 256 * t;
            if (AM == AM_TN) {
                int m = idx % BM, kp = idx / BM;
                int gm = bm + m, gk = k0 + 2 * kp;
                float x0 = (gm < M && gk     < K) ? Ab[(long)gk * M + gm]       : 0.f;
                float x1 = (gm < M && gk + 1 < K) ? Ab[(long)(gk + 1) * M + gm] : 0.f;
                rA[t] = make_float2(x0, x1);
            } else {
                int kp = idx & 7, m = idx >> 3;
                int gm = bm + m, gk = k0 + 2 * kp;
                float x0 = 0.f, x1 = 0.f;
                if (gm < M) {
                    if (gk + 1 < K) {
                        float2 v = *reinterpret_cast<const float2*>(&Ab[(long)gm * K + gk]);
                        x0 = v.x; x1 = v.y;
                    } else if (gk < K) {
                        x0 = Ab[(long)gm * K + gk];
                    }
                }
                rA[t] = make_float2(x0, x1);
                if (AM == AM_FUSED) {
                    float fa = 0.f, fb = 0.f;
                    if (gk + 1 < K) {
                        float2 v = *reinterpret_cast<const float2*>(&f2b[gk]);
                        fa = v.x; fb = v.y;
                    } else if (gk < K) {
                        fa = f2b[gk];
                    }
                    rF[t] = make_float2(fa, fb);
                }
            }
        }
    };
    auto loadB = [&](int k0) {
#pragma unroll
        for (int t = 0; t < BPL; t++) {
            int idx = tid + 256 * t;
            int n = idx % BN, kp = idx / BN;
            int gn = bn + n, gk = k0 + 2 * kp;
            float x0 = (gn < N && gk     < K) ? Bb[(long)gk * N + gn]       : 0.f;
            float x1 = (gn < N && gk + 1 < K) ? Bb[(long)(gk + 1) * N + gn] : 0.f;
            rB[t] = make_float2(x0, x1);
        }
    };
    auto storeAB = [&](int k0) {
#pragma unroll
        for (int t = 0; t < APL; t++) {
            int idx = tid + 256 * t;
            int kp, m;
            if (AM == AM_TN) { m = idx % BM; kp = idx / BM; }
            else             { kp = idx & 7; m = idx >> 3; }
            float x0 = rA[t].x, x1 = rA[t].y;
            if (AM == AM_FUSED) {
                int gk = k0 + 2 * kp;
                float e0 = s_f1[m] + rF[t].x; e0 = (e0 > 0.f) ? e0 : 0.2f * e0;
                if (!(x0 > 0.f)) e0 = -9e15f;
                float e1 = s_f1[m] + rF[t].y; e1 = (e1 > 0.f) ? e1 : 0.2f * e1;
                if (!(x1 > 0.f)) e1 = -9e15f;
                x0 = (gk     < K) ? __expf(e0 - s_m[m]) * s_i[m] : 0.f;
                x1 = (gk + 1 < K) ? __expf(e1 - s_m[m]) * s_i[m] : 0.f;
            }
            uint32_t hw, lw; pack_split(x0, x1, hw, lw);
            AsH[kp][m] = hw; AsL[kp][m] = lw;
        }
#pragma unroll
        for (int t = 0; t < BPL; t++) {
            int idx = tid + 256 * t;
            int n = idx % BN, kp = idx / BN;
            uint32_t hw, lw; pack_split(rB[t].x, rB[t].y, hw, lw);
            BsH[kp][n] = hw;
            if (!EXB) BsL[kp][n] = lw;
        }
    };

    loadA(0); loadB(0);
    __syncthreads();

    for (int k0 = 0; k0 < K; k0 += BK) {
        storeAB(k0);
        __syncthreads();
        if (k0 + BK < K) { loadA(k0 + BK); loadB(k0 + BK); }

        uint32_t ah[MT][4], al[MT][4], bh[NT][2], bl[NT][2];
#pragma unroll
        for (int mt = 0; mt < MT; mt++) {
            int r = wm + mt * 16;
            ah[mt][0] = AsH[lt    ][r + lg];
            ah[mt][1] = AsH[lt    ][r + lg + 8];
            ah[mt][2] = AsH[lt + 4][r + lg];
            ah[mt][3] = AsH[lt + 4][r + lg + 8];
            al[mt][0] = AsL[lt    ][r + lg];
            al[mt][1] = AsL[lt    ][r + lg + 8];
            al[mt][2] = AsL[lt + 4][r + lg];
            al[mt][3] = AsL[lt + 4][r + lg + 8];
        }
#pragma unroll
        for (int nt = 0; nt < NT; nt++) {
            int cidx = wn + nt * 8 + lg;
            bh[nt][0] = BsH[lt    ][cidx];
            bh[nt][1] = BsH[lt + 4][cidx];
            if (!EXB) {
                bl[nt][0] = BsL[lt    ][cidx];
                bl[nt][1] = BsL[lt + 4][cidx];
            }
        }
#define MMA_STEP(AF, BF)                                                        \
        asm volatile(                                                           \
            "mma.sync.aligned.m16n8k16.row.col.f32.f16.f16.f32 "                \
            "{%0,%1,%2,%3}, {%4,%5,%6,%7}, {%8,%9}, {%0,%1,%2,%3};"             \
            : "+f"(acc[mt][nt][0]), "+f"(acc[mt][nt][1]),                       \
              "+f"(acc[mt][nt][2]), "+f"(acc[mt][nt][3])                        \
            : "r"(AF[mt][0]), "r"(AF[mt][1]), "r"(AF[mt][2]), "r"(AF[mt][3]),   \
              "r"(BF[nt][0]), "r"(BF[nt][1]))
#pragma unroll
        for (int mt = 0; mt < MT; mt++)
#pragma unroll
            for (int nt = 0; nt < NT; nt++) {
                if (!EXB) MMA_STEP(ah, bl);
                MMA_STEP(al, bh);
                MMA_STEP(ah, bh);
            }
#undef MMA_STEP
        __syncthreads();
    }

#pragma unroll
    for (int mt = 0; mt < MT; mt++) {
#pragma unroll
        for (int nt = 0; nt < NT; nt++) {
            int gm = bm + wm + mt * 16 + lg;
            int gn = bn + wn + nt * 8 + 2 * lt;
            float v0 = acc[mt][nt][0], v1 = acc[mt][nt][1];
            float v2 = acc[mt][nt][2], v3 = acc[mt][nt][3];
            if (RELU) {
                v0 = v0 > 0.f ? v0 : 0.f;  v1 = v1 > 0.f ? v1 : 0.f;
                v2 = v2 > 0.f ? v2 : 0.f;  v3 = v3 > 0.f ? v3 : 0.f;
            }
            if (gm < M) {
                if (gn     < N) Cb[(long)gm * N + gn    ] = v0;
                if (gn + 1 < N) Cb[(long)gm * N + gn + 1] = v1;
            }
            if (gm + 8 < M) {
                if (gn     < N) Cb[(long)(gm + 8) * N + gn    ] = v2;
                if (gn + 1 < N) Cb[(long)(gm + 8) * N + gn + 1] = v3;
            }
        }
    }
}

// ---------------- row stats (layer 0 only) ----------------
__global__ void rowstat_k(const float* __restrict__ A,
                          const float* __restrict__ f1z, const float* __restrict__ f2z,
                          const float* __restrict__ f1s, const float* __restrict__ f2s,
                          float* __restrict__ mz, float* __restrict__ iz,
                          float* __restrict__ ms, float* __restrict__ is_, int N)
{
    int row = blockIdx.x;
    int b = row / N;
    const float* Ar = A + (size_t)row * N;
    const float* f2zb = f2z + (size_t)b * N;
    const float* f2sb = f2s + (size_t)b * N;
    float fz = f1z[row], fs = f1s[row];
    int t = threadIdx.x;
    float ez[4], es[4];
    float mzl = -1e30f, msl = -1e30f;
    double ss = 0.0;
#pragma unroll
    for (int it = 0; it < 4; it++) {
        int j = t + it * 256;
        float vz = -9e15f, vs = -9e15f;
        if (j < N) {
            float a = Ar[j];
            ss += (double)a * (double)a;
            bool on = a > 0.f;
            float xz = fz + f2zb[j];
            float xs = fs + f2sb[j];
            float lz = (xz > 0.f) ? xz : 0.2f * xz;
            float ls = (xs > 0.f) ? xs : 0.2f * xs;
            vz = on ? lz : -9e15f;
            vs = on ? ls : -9e15f;
        }
        ez[it] = vz; es[it] = vs;
        mzl = fmaxf(mzl, vz); msl = fmaxf(msl, vs);
    }
    __shared__ float sh[256];
    sh[t] = mzl; __syncthreads();
    for (int s = 128; s > 0; s >>= 1) { if (t < s) sh[t] = fmaxf(sh[t], sh[t + s]); __syncthreads(); }
    float Mz = sh[0]; __syncthreads();
    sh[t] = msl; __syncthreads();
    for (int s = 128; s > 0; s >>= 1) { if (t < s) sh[t] = fmaxf(sh[t], sh[t + s]); __syncthreads(); }
    float Ms = sh[0]; __syncthreads();

    float sz = 0.f, ssum = 0.f;
#pragma unroll
    for (int it = 0; it < 4; it++) {
        int j = t + it * 256;
        if (j < N) { sz += __expf(ez[it] - Mz); ssum += __expf(es[it] - Ms); }
    }
    sh[t] = sz; __syncthreads();
    for (int s = 128; s > 0; s >>= 1) { if (t < s) sh[t] += sh[t + s]; __syncthreads(); }
    float Sz = sh[0]; __syncthreads();
    sh[t] = ssum; __syncthreads();
    for (int s = 128; s > 0; s >>= 1) { if (t < s) sh[t] += sh[t + s]; __syncthreads(); }
    float Ss = sh[0]; __syncthreads();

    __shared__ double dh[256];
    dh[t] = ss; __syncthreads();
    for (int s = 128; s > 0; s >>= 1) { if (t < s) dh[t] += dh[t + s]; __syncthreads(); }

    if (t == 0) {
        mz[row] = Mz; iz[row] = 1.f / Sz;
        ms[row] = Ms; is_[row] = 1.f / Ss;
        atomicAdd(&g_tot, dh[0]);
    }
}

// ---------------- f1/f2, dual-target (blockIdx.y routes) ----------------
__device__ __forceinline__ void fvec_body(const float* __restrict__ Wh,
                                          const float* __restrict__ a,
                                          float* __restrict__ f1, float* __restrict__ f2,
                                          int rows, int F)
{
    int w = (blockIdx.x * blockDim.x + threadIdx.x) >> 5;
    int lane = threadIdx.x & 31;
    if (w >= rows) return;
    const float* p = Wh + (size_t)w * F;
    float s1 = 0.f, s2 = 0.f;
    for (int f = lane; f < F; f += 32) {
        float v = p[f];
        s1 += v * a[f];
        s2 += v * a[F + f];
    }
#pragma unroll
    for (int o = 16; o > 0; o >>= 1) {
        s1 += __shfl_down_sync(0xffffffffu, s1, o);
        s2 += __shfl_down_sync(0xffffffffu, s2, o);
    }
    if (lane == 0) { f1[w] = s1; f2[w] = s2; }
}

__global__ void fvec2_k(const float* WhA, const float* aA, float* f1A, float* f2A, int FA,
                        const float* WhB, const float* aB, float* f1B, float* f2B, int FB,
                        int rows)
{
    if (blockIdx.y == 0) fvec_body(WhA, aA, f1A, f2A, rows, FA);
    else                 fvec_body(WhB, aB, f1B, f2B, rows, FB);
}

// ---------------- softmax over c + entropy (layer 0) ----------------
__global__ void softmax_c_ent(float* __restrict__ S, int rows, int c, double inv_rows)
{
    int w = (blockIdx.x * blockDim.x + threadIdx.x) >> 5;
    int lane = threadIdx.x & 31;
    if (w >= rows) return;
    float* p = S + (size_t)w * c;
    float v[2] = {-1e30f, -1e30f};
    float m = -1e30f;
#pragma unroll
    for (int i = 0; i < 2; i++) {
        int f = lane + 32 * i;
        if (f < c) { v[i] = p[f]; m = fmaxf(m, v[i]); }
    }
#pragma unroll
    for (int o = 16; o > 0; o >>= 1) m = fmaxf(m, __shfl_xor_sync(0xffffffffu, m, o));
    float s = 0.f;
#pragma unroll
    for (int i = 0; i < 2; i++) {
        int f = lane + 32 * i;
        if (f < c) { v[i] = __expf(v[i] - m); s += v[i]; }
    }
#pragma unroll
    for (int o = 16; o > 0; o >>= 1) s += __shfl_xor_sync(0xffffffffu, s, o);
    float inv = 1.f / s;
    double erow = 0.0;
#pragma unroll
    for (int i = 0; i < 2; i++) {
        int f = lane + 32 * i;
        if (f < c) {
            float q = v[i] * inv;
            p[f] = q;
            erow += -(double)q * (double)logf(q + 1e-15f);
        }
    }
#pragma unroll
    for (int o = 16; o > 0; o >>= 1) erow += __shfl_down_sync(0xffffffffu, erow, o);
    if (lane == 0) atomicAdd(&g_ent, erow * inv_rows);
}

__global__ void k_zero_losses() { g_link = 0.0; g_ent = 0.0; g_tot = 0.0; g_tot1 = 0.0; g_tot2 = 0.0; }

// ---------------- fused layers 1+2 tail (fp32, one block per batch) ----------------
#define FUSED_SMEM_FLOATS 49664

__global__ __launch_bounds__(256)
void fused_tail_k(const float* __restrict__ Whz1g, const float* __restrict__ Whs1g,
                  const float* __restrict__ A1g,
                  const float* __restrict__ f1zg, const float* __restrict__ f2zg,
                  const float* __restrict__ f1sg, const float* __restrict__ f2sg,
                  const float* __restrict__ Wg2, const float* __restrict__ ag2,
                  const float* __restrict__ Ws2, const float* __restrict__ as2,
                  const float* __restrict__ Wd, const float* __restrict__ bd,
                  float* __restrict__ out, int out_size)
{
    const int b = blockIdx.x, tid = threadIdx.x;
    const int warp = tid >> 5, lane = tid & 31;
    extern __shared__ float sm[];
    float* sWh  = sm;
    float* sZ   = sWh  + 16384;
    float* sA   = sZ   + 16384;
    float* sE   = sA   + 4096;
    float* sX2  = sE   + 4096;
    float* sWh2 = sX2  + 2048;
    float* sZ2  = sWh2 + 2048;
    float* sWhs = sZ2  + 2048;
    float* sS   = sWhs + 512;
    float* sT   = sS   + 512;
    float* sf1  = sT   + 512;
    float* sf2  = sf1  + 64;
    float* sg1  = sf2  + 64;
    float* sg2  = sg1  + 64;
    float* sA2  = sg2  + 64;
    float* sX3  = sA2  + 64;
    float* sWhs2= sX3  + 256;
    float* sP2  = sWhs2+ 8;
    float* sf1b = sP2  + 64;
    float* sf2b = sf1b + 8;
    float* sf1c = sf2b + 8;
    float* sf2c = sf1c + 8;
    float* sred = sf2c + 8;

    for (int i = tid; i < 64 * 256; i += 256) sWh[i] = Whz1g[(size_t)b * 16384 + i];
    for (int i = tid; i < 4096; i += 256)     sA[i]  = A1g [(size_t)b * 4096 + i];
    for (int i = tid; i < 512; i += 256)      sWhs[i] = Whs1g[(size_t)b * 512 + i];
    if (tid < 64) {
        sf1[tid] = f1zg[b * 64 + tid]; sf2[tid] = f2zg[b * 64 + tid];
        sg1[tid] = f1sg[b * 64 + tid]; sg2[tid] = f2sg[b * 64 + tid];
    }
    __syncthreads();

    for (int r = warp * 8; r < warp * 8 + 8; r++) {
        float f1i = sf1[r];
        float e0, e1;
        {
            int j = lane;
            float x = f1i + sf2[j]; x = (x > 0.f) ? x : 0.2f * x;
            e0 = (sA[r * 64 + j] > 0.f) ? x : -9e15f;
            j = lane + 32;
            x = f1i + sf2[j]; x = (x > 0.f) ? x : 0.2f * x;
            e1 = (sA[r * 64 + j] > 0.f) ? x : -9e15f;
        }
        float m = fmaxf(e0, e1);
#pragma unroll
        for (int o = 16; o > 0; o >>= 1) m = fmaxf(m, __shfl_xor_sync(0xffffffffu, m, o));
        float p0 = __expf(e0 - m), p1 = __expf(e1 - m);
        float s = p0 + p1;
#pragma unroll
        for (int o = 16; o > 0; o >>= 1) s += __shfl_xor_sync(0xffffffffu, s, o);
        float inv = 1.f / s;
        sE[r * 64 + lane] = p0 * inv;
        sE[r * 64 + lane + 32] = p1 * inv;
    }
    __syncthreads();

    for (int n0 = 0; n0 < 64; n0 += 16) {
        float acc[16];
#pragma unroll
        for (int i = 0; i < 16; i++) acc[i] = 0.f;
        for (int k = 0; k < 64; k++) {
            float whv = sWh[k * 256 + tid];
#pragma unroll
            for (int i = 0; i < 16; i++) acc[i] += sE[(n0 + i) * 64 + k] * whv;
        }
#pragma unroll
        for (int i = 0; i < 16; i++) sZ[(n0 + i) * 256 + tid] = fmaxf(acc[i], 0.f);
    }
    __syncthreads();

    for (int r = warp * 8; r < warp * 8 + 8; r++) {
        float f1i = sg1[r];
        float e0, e1;
        {
            int j = lane;
            float x = f1i + sg2[j]; x = (x > 0.f) ? x : 0.2f * x;
            e0 = (sA[r * 64 + j] > 0.f) ? x : -9e15f;
            j = lane + 32;
            x = f1i + sg2[j]; x = (x > 0.f) ? x : 0.2f * x;
            e1 = (sA[r * 64 + j] > 0.f) ? x : -9e15f;
        }
        float m = fmaxf(e0, e1);
#pragma unroll
        for (int o = 16; o > 0; o >>= 1) m = fmaxf(m, __shfl_xor_sync(0xffffffffu, m, o));
        float p0 = __expf(e0 - m), p1 = __expf(e1 - m);
        float s = p0 + p1;
#pragma unroll
        for (int o = 16; o > 0; o >>= 1) s += __shfl_xor_sync(0xffffffffu, s, o);
        float inv = 1.f / s;
        sE[r * 64 + lane] = p0 * inv;
        sE[r * 64 + lane + 32] = p1 * inv;
    }
    __syncthreads();

    for (int idx = tid; idx < 512; idx += 256) {
        int n = idx >> 3, cc = idx & 7;
        float s = 0.f;
        for (int j = 0; j < 64; j++) s += sE[n * 64 + j] * sWhs[j * 8 + cc];
        sS[idx] = fmaxf(s, 0.f);
    }
    __syncthreads();

    if (tid < 64) {
        float v[8]; float m = -1e30f;
#pragma unroll
        for (int c = 0; c < 8; c++) { v[c] = sS[tid * 8 + c]; m = fmaxf(m, v[c]); }
        float s = 0.f;
#pragma unroll
        for (int c = 0; c < 8; c++) { v[c] = __expf(v[c] - m); s += v[c]; }
        float inv = 1.f / s;
        float ent = 0.f;
#pragma unroll
        for (int c = 0; c < 8; c++) {
            float q = v[c] * inv;
            sS[tid * 8 + c] = q;
            ent += -q * logf(q + 1e-15f);
        }
        sred[tid] = ent;
    }
    __syncthreads();
    if (tid == 0) {
        double e = 0.0;
        for (int i = 0; i < 64; i++) e += (double)sred[i];
        atomicAdd(&g_ent, e / 1024.0);
    }

    for (int idx = tid; idx < 2048; idx += 256) {
        int c = idx >> 8, f = idx & 255;
        float s = 0.f;
        for (int n = 0; n < 64; n++) s += sS[n * 8 + c] * sZ[n * 256 + f];
        sX2[idx] = s;
    }
    for (int idx = tid; idx < 512; idx += 256) {
        int c = idx >> 6, j = idx & 63;
        float s = 0.f;
        for (int n = 0; n < 64; n++) s += sS[n * 8 + c] * sA[n * 64 + j];
        sT[idx] = s;
    }
    __syncthreads();
    if (tid < 64) {
        int c = tid >> 3, d = tid & 7;
        float s = 0.f;
        for (int j = 0; j < 64; j++) s += sT[c * 64 + j] * sS[j * 8 + d];
        sA2[tid] = s;
    }
    {
        float lsum = 0.f;
        for (int idx = tid; idx < 4096; idx += 256) {
            int i = idx >> 6, j = idx & 63;
            float d = 0.f;
#pragma unroll
            for (int c = 0; c < 8; c++) d += sS[i * 8 + c] * sS[j * 8 + c];
            float df = sA[idx] - d;
            lsum += df * df;
        }
        sred[tid] = lsum; __syncthreads();
        for (int r = 128; r > 0; r >>= 1) { if (tid < r) sred[tid] += sred[tid + r]; __syncthreads(); }
        if (tid == 0) atomicAdd(&g_tot1, (double)sred[0]);
    }
    __syncthreads();

    {
        float acc[8];
#pragma unroll
        for (int i = 0; i < 8; i++) acc[i] = 0.f;
        for (int k = 0; k < 256; k++) {
            float wg = Wg2[k * 256 + tid];
#pragma unroll
            for (int n = 0; n < 8; n++) acc[n] += sX2[n * 256 + k] * wg;
        }
#pragma unroll
        for (int n = 0; n < 8; n++) sWh2[n * 256 + tid] = acc[n];
    }
    {
        float p = 0.f;
        for (int k = lane; k < 256; k += 32) p += sX2[warp * 256 + k] * Ws2[k];
#pragma unroll
        for (int o = 16; o > 0; o >>= 1) p += __shfl_down_sync(0xffffffffu, p, o);
        if (lane == 0) sWhs2[warp] = p;
    }
    __syncthreads();
    {
        float p1 = 0.f, p2 = 0.f;
        for (int k = lane; k < 256; k += 32) {
            float v = sWh2[warp * 256 + k];
            p1 += v * ag2[k];
            p2 += v * ag2[256 + k];
        }
#pragma unroll
        for (int o = 16; o > 0; o >>= 1) {
            p1 += __shfl_down_sync(0xffffffffu, p1, o);
            p2 += __shfl_down_sync(0xffffffffu, p2, o);
        }
        if (lane == 0) { sf1b[warp] = p1; sf2b[warp] = p2; }
    }
    if (tid < 8) {
        sf1c[tid] = sWhs2[tid] * as2[0];
        sf2c[tid] = sWhs2[tid] * as2[1];
    }
    __syncthreads();
    if (tid < 8) {
        float e[8]; float m = -1e30f;
#pragma unroll
        for (int j = 0; j < 8; j++) {
            float x = sf1b[tid] + sf2b[j]; x = (x > 0.f) ? x : 0.2f * x;
            e[j] = (sA2[tid * 8 + j] > 0.f) ? x : -9e15f;
            m = fmaxf(m, e[j]);
        }
        float s = 0.f;
#pragma unroll
        for (int j = 0; j < 8; j++) { e[j] = __expf(e[j] - m); s += e[j]; }
        float inv = 1.f / s;
#pragma unroll
        for (int j = 0; j < 8; j++) sP2[tid * 8 + j] = e[j] * inv;
    }
    __syncthreads();
    {
#pragma unroll
        for (int n = 0; n < 8; n++) {
            float z = 0.f;
#pragma unroll
            for (int k = 0; k < 8; k++) z += sP2[n * 8 + k] * sWh2[k * 256 + tid];
            sZ2[n * 256 + tid] = fmaxf(z, 0.f);
        }
    }
    __syncthreads();
    {
        float s = 0.f;
#pragma unroll
        for (int n = 0; n < 8; n++) s += sZ2[n * 256 + tid];
        sX3[tid] = s;
    }
    if (tid < 64) {
        float d = sA2[tid] - 1.f;
        sred[tid] = d * d;
    } else sred[tid] = 0.f;
    __syncthreads();
    for (int r = 128; r > 0; r >>= 1) { if (tid < r) sred[tid] += sred[tid + r]; __syncthreads(); }
    if (tid == 0) {
        atomicAdd(&g_tot2, (double)sred[0]);
        float a3 = 0.f;
        for (int i = 0; i < 64; i++) a3 += sA2[i];
        if (160 + b < out_size) out[160 + b] = a3;
    }
    __syncthreads();
    if (tid < NCLASS) {
        float v = bd[tid];
        for (int f = 0; f < 256; f++) v += sX3[f] * Wd[f * NCLASS + tid];
        if (b * NCLASS + tid < out_size) out[b * NCLASS + tid] = v;
    }
}

// ---------------- final: link0 reduction + write losses (merged) ----------------
__global__ void tail_fin(const float* __restrict__ Ap, const float* __restrict__ G,
                         float* __restrict__ out, int out_size)
{
    int t = threadIdx.x;
    double s = 0.0;
    for (int idx = t; idx < BATCH * 64; idx += 256) {
        int b = idx / 64, j = idx % 64;
        s += -2.0 * (double)Ap[((long)b * 64 + j) * 64 + j];
    }
    for (int idx = t; idx < BATCH * 64 * 64; idx += 256) {
        double g = G[idx]; s += g * g;
    }
    __shared__ double sh[256];
    sh[t] = s; __syncthreads();
    for (int r = 128; r > 0; r >>= 1) { if (t < r) sh[t] += sh[t + r]; __syncthreads(); }
    if (t == 0) {
        double v0 = g_tot + sh[0];
        double t1 = g_tot1, t2 = g_tot2;
        double link = sqrt(v0 > 0.0 ? v0 : 0.0) / (double)((long)BATCH * 1024 * 1024)
                    + sqrt(t1 > 0.0 ? t1 : 0.0) / 65536.0
                    + sqrt(t2 > 0.0 ? t2 : 0.0) / 1024.0;
        if (176 < out_size) out[176] = (float)link;
        if (177 < out_size) out[177] = (float)g_ent;
    }
}

#define NOF nullptr, nullptr, nullptr, nullptr

extern "C" void kernel_launch(void* const* d_in, const int* in_sizes, int n_in,
                              void* d_out, int out_size)
{
    (void)in_sizes; (void)n_in;
    const float* X  = (const float*)d_in[0];
    const float* A  = (const float*)d_in[1];
    const float* Wg0 = (const float*)d_in[2];
    const float* ag0 = (const float*)d_in[3];
    const float* Ws0 = (const float*)d_in[4];
    const float* as0 = (const float*)d_in[5];
    const float* Wg1 = (const float*)d_in[6];
    const float* ag1 = (const float*)d_in[7];
    const float* Ws1 = (const float*)d_in[8];
    const float* as1 = (const float*)d_in[9];
    const float* Wg2 = (const float*)d_in[10];
    const float* ag2 = (const float*)d_in[11];
    const float* Ws2 = (const float*)d_in[12];
    const float* as2 = (const float*)d_in[13];
    const float* Wd = (const float*)d_in[14];
    const float* bd = (const float*)d_in[15];
    float* out = (float*)d_out;

    float *whz, *whs, *z, *s, *t, *gg, *xp, *ap;
    float *f1z, *f2z, *f1s, *f2s, *mz, *iz, *ms, *is_;
    cudaGetSymbolAddress((void**)&whz, g_Whz);
    cudaGetSymbolAddress((void**)&whs, g_Whs);
    cudaGetSymbolAddress((void**)&z,   g_Zb);
    cudaGetSymbolAddress((void**)&s,   g_Sb);
    cudaGetSymbolAddress((void**)&t,   g_Tb);
    cudaGetSymbolAddress((void**)&gg,  g_Gb);
    cudaGetSymbolAddress((void**)&xp,  g_Xp);
    cudaGetSymbolAddress((void**)&ap,  g_Ap);
    cudaGetSymbolAddress((void**)&f1z, g_f1z);
    cudaGetSymbolAddress((void**)&f2z, g_f2z);
    cudaGetSymbolAddress((void**)&f1s, g_f1s);
    cudaGetSymbolAddress((void**)&f2s, g_f2s);
    cudaGetSymbolAddress((void**)&mz,  g_mz);
    cudaGetSymbolAddress((void**)&iz,  g_iz);
    cudaGetSymbolAddress((void**)&ms,  g_ms);
    cudaGetSymbolAddress((void**)&is_, g_is);

    static bool init_done = false;
    static cudaStream_t s2 = nullptr;
    static cudaEvent_t ev0, ev1, ev2, ev3, ev4, ev5;
    const int FUSED_SMEM = FUSED_SMEM_FLOATS * (int)sizeof(float);
    if (!init_done) {
        cudaFuncSetAttribute(fused_tail_k, cudaFuncAttributeMaxDynamicSharedMemorySize, FUSED_SMEM);
        cudaStreamCreateWithFlags(&s2, cudaStreamNonBlocking);
        cudaEventCreateWithFlags(&ev0, cudaEventDisableTiming);
        cudaEventCreateWithFlags(&ev1, cudaEventDisableTiming);
        cudaEventCreateWithFlags(&ev2, cudaEventDisableTiming);
        cudaEventCreateWithFlags(&ev3, cudaEventDisableTiming);
        cudaEventCreateWithFlags(&ev4, cudaEventDisableTiming);
        cudaEventCreateWithFlags(&ev5, cudaEventDisableTiming);
        init_done = true;
    }

    const int N0 = 1024;

    k_zero_losses<<<1, 1>>>();
    cudaEventRecord(ev0, 0);
    cudaStreamWaitEvent(s2, ev0, 0);

    // s0: Whz = X @ Wg0    |    s2: Whs = X @ Ws0
    {
        dim3 g(2, 8, BATCH);
        mma_k<128, 128, 2, 4, AM_NN, false, false><<<g, 256>>>(X, Wg0, whz, N0, 256, 128,
            (long)N0 * 128, 0, (long)N0 * 256, NOF);
    }
    {
        dim3 g(1, 8, BATCH);
        mma_k<128, 64, 2, 4, AM_NN, false, false><<<g, 256, 0, s2>>>(X, Ws0, whs, N0, 64, 128,
            (long)N0 * 128, 0, (long)N0 * 64, NOF);
    }
    cudaEventRecord(ev1, s2);
    cudaStreamWaitEvent(0, ev1, 0);

    // s0: fvec + rowstat (need both Wh)
    {
        int rows = BATCH * N0;
        dim3 g((rows * 32 + 255) / 256, 2);
        fvec2_k<<<g, 256>>>(whz, ag0, f1z, f2z, 256, whs, as0, f1s, f2s, 64, rows);
    }
    rowstat_k<<<BATCH * N0, 256>>>(A, f1z, f2z, f1s, f2s, mz, iz, ms, is_, N0);
    cudaEventRecord(ev2, 0);
    cudaStreamWaitEvent(s2, ev2, 0);

    // s0: Zagg             |    s2: Sagg -> softmax
    {
        dim3 g(2, 8, BATCH);
        mma_k<128, 128, 2, 4, AM_FUSED, true, false><<<g, 256>>>(A, whz, z, N0, 256, N0,
            (long)N0 * N0, (long)N0 * 256, (long)N0 * 256, f1z, f2z, mz, iz);
    }
    cudaEventRecord(ev3, 0);
    {
        dim3 g(1, 8, BATCH);
        mma_k<128, 64, 2, 4, AM_FUSED, true, false><<<g, 256, 0, s2>>>(A, whs, s, N0, 64, N0,
            (long)N0 * N0, (long)N0 * 64, (long)N0 * 64, f1s, f2s, ms, is_);
    }
    softmax_c_ent<<<(BATCH * N0 + 7) / 8, 256, 0, s2>>>(s, BATCH * N0, 64, 1.0 / (double)(BATCH * N0));
    cudaEventRecord(ev4, s2);
    cudaStreamWaitEvent(0, ev4, 0);
    cudaStreamWaitEvent(s2, ev3, 0);

    // s0: T -> G -> A1     |    s2: X1 -> Whz1 -> Whs1 -> fvec1
    {
        dim3 g(8, 1, BATCH);
        mma_k<64, 128, 2, 4, AM_TN, false, true><<<g, 256>>>(s, A, t, 64, N0, N0,
            (long)N0 * 64, (long)N0 * N0, (long)64 * N0, NOF);
    }
    {
        dim3 g(1, 1, BATCH);
        mma_k<64, 128, 2, 4, AM_TN, false, false><<<g, 256>>>(s, s, gg, 64, 64, N0,
            (long)N0 * 64, (long)N0 * 64, (long)64 * 64, NOF);
    }
    {
        dim3 g(1, 1, BATCH);
        mma_k<64, 128, 2, 4, AM_NN, false, false><<<g, 256>>>(t, s, ap, 64, 64, N0,
            (long)64 * N0, (long)N0 * 64, (long)64 * 64, NOF);
    }
    {   // X1 = S^T Z (s2; has ev3 for Z, s-order for S)
        dim3 g(2, 1, BATCH);
        mma_k<64, 128, 2, 4, AM_TN, false, false><<<g, 256, 0, s2>>>(s, z, xp, 64, 256, N0,
            (long)N0 * 64, (long)N0 * 256, (long)64 * 256, NOF);
    }
    {   // Whz1 = X1 @ Wg1 (s2; whz safe: fvec2 done before ev2, Zagg done before ev3)
        dim3 g(2, 1, BATCH);
        mma_k<128, 128, 2, 4, AM_NN, false, false><<<g, 256, 0, s2>>>(xp, Wg1, whz, 64, 256, 256,
            (long)64 * 256, 0, (long)64 * 256, NOF);
    }
    {   // Whs1 = X1 @ Ws1 (s2; whs safe: Sagg done on s2)
        dim3 g(1, 1, BATCH);
        mma_k<128, 64, 2, 4, AM_NN, false, false><<<g, 256, 0, s2>>>(xp, Ws1, whs, 64, 8, 256,
            (long)64 * 256, 0, (long)64 * 8, NOF);
    }
    {   // fvec layer1 (s2)
        int rows = BATCH * 64;
        dim3 g((rows * 32 + 255) / 256, 2);
        fvec2_k<<<g, 256, 0, s2>>>(whz, ag1, f1z, f2z, 256, whs, as1, f1s, f2s, 8, rows);
    }
    cudaEventRecord(ev5, s2);
    cudaStreamWaitEvent(0, ev5, 0);

    // s0: fused tail + losses (ap from s0 order, whz/whs/fvecs from ev5)
    fused_tail_k<<<BATCH, 256, FUSED_SMEM>>>(whz, whs, ap, f1z, f2z, f1s, f2s,
                                             Wg2, ag2, Ws2, as2, Wd, bd, out, out_size);
    tail_fin<<<1, 256>>>(ap, gg, out, out_size);
}